// round 4
// baseline (speedup 1.0000x reference)
#include <cuda_runtime.h>

// CharRNN: 3-layer tanh RNN, B=512, T=1024, HID=100, VOCAB=62.
// R4: in-warp k-split (shfl reduction, no scratch), double-buffered h,
//     3 barriers/step (dec(t-1) merged with l1(t)), Wh1+Wdec rows in
//     registers, fast tanh via __expf.

#define BB    512
#define TT    1024
#define HID   100
#define VOCAB 62
#define NL    3
#define ROWS  4
#define NCTA  (BB / ROWS)       // 128
#define NTHR  256
#define SJ    104               // padded row stride (floats)

// ---- shared memory layout (floats) ----
#define OFF_WI2  0              // 100 x SJ
#define OFF_WH2  10400
#define OFF_WI3  20800
#define OFF_WH3  31200
#define OFF_H    41600          // [2 buf][3 layer][4 rows][SJ]
#define SMEM_FLOATS (OFF_H + 2 * 3 * ROWS * SJ)   // 44096 -> 176,384 B

__device__ float g_table[VOCAB * HID];  // emb@Wi1^T + b_ih1 + b_hh1

// ---------------------------------------------------------------------------
__global__ void table_kernel(const float* __restrict__ emb,
                             const float* __restrict__ W_ih,
                             const float* __restrict__ b_ih,
                             const float* __restrict__ b_hh) {
    int v = blockIdx.x;
    int j = threadIdx.x;
    if (j >= HID) return;
    float acc = b_ih[j] + b_hh[j];
    const float* e = emb + v * HID;
    const float* w = W_ih + j * HID;
#pragma unroll
    for (int k = 0; k < HID; k++) acc += e[k] * w[k];
    g_table[v * HID + j] = acc;
}

// ---------------------------------------------------------------------------
__device__ __forceinline__ void fma2(unsigned long long& acc,
                                     unsigned long long a,
                                     unsigned long long b) {
    asm("fma.rn.f32x2 %0, %1, %2, %3;" : "=l"(acc) : "l"(a), "l"(b), "l"(acc));
}
__device__ __forceinline__ float hadd2(unsigned long long a) {
    float lo = __uint_as_float((unsigned)a);
    float hi = __uint_as_float((unsigned)(a >> 32));
    return lo + hi;
}
__device__ __forceinline__ float tanho(float x) {
    float e = __expf(2.0f * x);
    return 1.0f - __fdividef(2.0f, e + 1.0f);
}

// ---------------------------------------------------------------------------
__global__ __launch_bounds__(NTHR, 1)
void rnn_kernel(const int*   __restrict__ ids,
                const float* __restrict__ W_ih,
                const float* __restrict__ W_hh,
                const float* __restrict__ b_ih,
                const float* __restrict__ b_hh,
                const float* __restrict__ W_dec,
                const float* __restrict__ b_dec,
                float* __restrict__ logits,
                float* __restrict__ hidden) {
    extern __shared__ float s[];
    const int tid  = threadIdx.x;
    const int wid  = tid >> 5;
    const int lane = tid & 31;
    const int m    = lane >> 1;        // neuron slot within warp
    const int p    = lane & 1;         // k-half: 0 -> k[0,52), 1 -> k[52,104)
    const int b0   = blockIdx.x * ROWS;
    const int kh   = p * 52;           // float offset of my k-half

    const int j1  = wid * 13 + m;                       // layer neuron
    const int j1c = (j1 < HID) ? j1 : (HID - 1);
    const bool w1act = (p == 0) && (m < 13) && (j1 < HID);
    const int jd  = wid * 8 + m;                        // decoder neuron
    const int jdc = (jd < VOCAB) ? jd : (VOCAB - 1);
    const bool wdact = (p == 0) && (m < 8) && (jd < VOCAB);

    // ---- stage smem weights (stride SJ, zero-padded cols 100..103) ----
    for (int i = tid; i < HID * SJ; i += NTHR) {
        int row = i / SJ, col = i - row * SJ;
        float vi2 = 0.f, vh2 = 0.f, vi3 = 0.f, vh3 = 0.f;
        if (col < HID) {
            vi2 = W_ih[1 * HID * HID + row * HID + col];
            vh2 = W_hh[1 * HID * HID + row * HID + col];
            vi3 = W_ih[2 * HID * HID + row * HID + col];
            vh3 = W_hh[2 * HID * HID + row * HID + col];
        }
        s[OFF_WI2 + i] = vi2;
        s[OFF_WH2 + i] = vh2;
        s[OFF_WI3 + i] = vi3;
        s[OFF_WH3 + i] = vh3;
    }
    for (int i = tid; i < 2 * NL * ROWS * SJ; i += NTHR) s[OFF_H + i] = 0.0f;

    // ---- register weights: Wh1 row-half, Wdec row-half ----
    ulonglong2 w1r[13], wdr[13];
    {
        const ulonglong2* src1 = reinterpret_cast<const ulonglong2*>(W_hh + j1c * HID + kh);
        const ulonglong2* srcd = reinterpret_cast<const ulonglong2*>(W_dec + jdc * HID + kh);
        const int nv = p ? 12 : 13;    // hi half: 48 floats + one zero vec4
#pragma unroll
        for (int kc = 0; kc < 13; kc++) {
            if (kc < nv) { w1r[kc] = src1[kc]; wdr[kc] = srcd[kc]; }
            else { w1r[kc] = make_ulonglong2(0, 0); wdr[kc] = make_ulonglong2(0, 0); }
        }
    }
    const float b2r = b_ih[1 * HID + j1c] + b_hh[1 * HID + j1c];
    const float b3r = b_ih[2 * HID + j1c] + b_hh[2 * HID + j1c];
    const float bdr = b_dec[jdc];

    // weight smem row pointers (my k-half)
    const float* wi2row = s + OFF_WI2 + j1c * SJ + kh;
    const float* wh2row = s + OFF_WH2 + j1c * SJ + kh;
    const float* wi3row = s + OFF_WI3 + j1c * SJ + kh;
    const float* wh3row = s + OFF_WH3 + j1c * SJ + kh;

    // first-step tokens
    int tok[ROWS];
#pragma unroll
    for (int r = 0; r < ROWS; r++) tok[r] = ids[(b0 + r) * TT];

    __syncthreads();

    for (int t = 0; t < TT; t++) {
        const int ro = t & 1, wo = ro ^ 1;
        float* h1o = s + OFF_H + (ro * NL + 0) * ROWS * SJ;
        float* h2o = s + OFF_H + (ro * NL + 1) * ROWS * SJ;
        float* h3o = s + OFF_H + (ro * NL + 2) * ROWS * SJ;
        float* h1n = s + OFF_H + (wo * NL + 0) * ROWS * SJ;
        float* h2n = s + OFF_H + (wo * NL + 1) * ROWS * SJ;
        float* h3n = s + OFF_H + (wo * NL + 2) * ROWS * SJ;

        // token-table inputs for layer 1 (this step's tokens)
        float tbl[ROWS];
#pragma unroll
        for (int r = 0; r < ROWS; r++) tbl[r] = g_table[tok[r] * HID + j1c];

        // ========= phase A: layer-1(t) dot + decoder(t-1) dot =========
        {
            unsigned long long a1[ROWS] = {0, 0, 0, 0};
            unsigned long long ad[ROWS] = {0, 0, 0, 0};
#pragma unroll
            for (int kc = 0; kc < 13; kc++) {
                ulonglong2 w1 = w1r[kc];
                ulonglong2 wd = wdr[kc];
#pragma unroll
                for (int r = 0; r < ROWS; r++) {
                    ulonglong2 h1 = *reinterpret_cast<const ulonglong2*>(h1o + r * SJ + kh + kc * 4);
                    ulonglong2 h3 = *reinterpret_cast<const ulonglong2*>(h3o + r * SJ + kh + kc * 4);
                    fma2(a1[r], w1.x, h1.x); fma2(a1[r], w1.y, h1.y);
                    fma2(ad[r], wd.x, h3.x); fma2(ad[r], wd.y, h3.y);
                }
            }
#pragma unroll
            for (int r = 0; r < ROWS; r++) {
                float s1 = hadd2(a1[r]);
                s1 += __shfl_xor_sync(0xffffffffu, s1, 1);
                float sd = hadd2(ad[r]);
                sd += __shfl_xor_sync(0xffffffffu, sd, 1);
                if (w1act) h1n[r * SJ + j1] = tanho(tbl[r] + s1);
                if (wdact && t > 0)
                    logits[((size_t)(b0 + r) * TT + (t - 1)) * VOCAB + jd] = bdr + sd;
            }
        }
        __syncthreads();

        // ========= phase B: layer-2 =========
        {
            unsigned long long a[ROWS] = {0, 0, 0, 0};
#pragma unroll
            for (int kc = 0; kc < 13; kc++) {
                ulonglong2 wi = *reinterpret_cast<const ulonglong2*>(wi2row + kc * 4);
                ulonglong2 wh = *reinterpret_cast<const ulonglong2*>(wh2row + kc * 4);
#pragma unroll
                for (int r = 0; r < ROWS; r++) {
                    ulonglong2 hx = *reinterpret_cast<const ulonglong2*>(h1n + r * SJ + kh + kc * 4);
                    ulonglong2 hh = *reinterpret_cast<const ulonglong2*>(h2o + r * SJ + kh + kc * 4);
                    fma2(a[r], wi.x, hx.x); fma2(a[r], wi.y, hx.y);
                    fma2(a[r], wh.x, hh.x); fma2(a[r], wh.y, hh.y);
                }
            }
#pragma unroll
            for (int r = 0; r < ROWS; r++) {
                float sv = hadd2(a[r]);
                sv += __shfl_xor_sync(0xffffffffu, sv, 1);
                if (w1act) h2n[r * SJ + j1] = tanho(b2r + sv);
            }
        }
        __syncthreads();

        // ========= phase C: layer-3 (+ prefetch next tokens) =========
        {
            const int tn = (t + 1 < TT) ? (t + 1) : t;
#pragma unroll
            for (int r = 0; r < ROWS; r++) tok[r] = ids[(b0 + r) * TT + tn];

            unsigned long long a[ROWS] = {0, 0, 0, 0};
#pragma unroll
            for (int kc = 0; kc < 13; kc++) {
                ulonglong2 wi = *reinterpret_cast<const ulonglong2*>(wi3row + kc * 4);
                ulonglong2 wh = *reinterpret_cast<const ulonglong2*>(wh3row + kc * 4);
#pragma unroll
                for (int r = 0; r < ROWS; r++) {
                    ulonglong2 hx = *reinterpret_cast<const ulonglong2*>(h2n + r * SJ + kh + kc * 4);
                    ulonglong2 hh = *reinterpret_cast<const ulonglong2*>(h3o + r * SJ + kh + kc * 4);
                    fma2(a[r], wi.x, hx.x); fma2(a[r], wi.y, hx.y);
                    fma2(a[r], wh.x, hh.x); fma2(a[r], wh.y, hh.y);
                }
            }
#pragma unroll
            for (int r = 0; r < ROWS; r++) {
                float sv = hadd2(a[r]);
                sv += __shfl_xor_sync(0xffffffffu, sv, 1);
                if (w1act) h3n[r * SJ + j1] = tanho(b3r + sv);
            }
        }
        __syncthreads();
    }

    // ---- final decoder for t = TT-1 (h3 final lives in buffer 0) ----
    {
        const float* h3f = s + OFF_H + (0 * NL + 2) * ROWS * SJ;
        unsigned long long ad[ROWS] = {0, 0, 0, 0};
#pragma unroll
        for (int kc = 0; kc < 13; kc++) {
            ulonglong2 wd = wdr[kc];
#pragma unroll
            for (int r = 0; r < ROWS; r++) {
                ulonglong2 h3 = *reinterpret_cast<const ulonglong2*>(h3f + r * SJ + kh + kc * 4);
                fma2(ad[r], wd.x, h3.x); fma2(ad[r], wd.y, h3.y);
            }
        }
#pragma unroll
        for (int r = 0; r < ROWS; r++) {
            float sd = hadd2(ad[r]);
            sd += __shfl_xor_sync(0xffffffffu, sd, 1);
            if (wdact)
                logits[((size_t)(b0 + r) * TT + (TT - 1)) * VOCAB + jd] = bdr + sd;
        }
    }

    // ---- final hidden states [NL, B, HID] (buffer 0) ----
    if (w1act) {
#pragma unroll
        for (int l = 0; l < NL; l++) {
            const float* hf = s + OFF_H + (0 * NL + l) * ROWS * SJ;
#pragma unroll
            for (int r = 0; r < ROWS; r++)
                hidden[(size_t)(l * BB + b0 + r) * HID + j1] = hf[r * SJ + j1];
        }
    }
}

// ---------------------------------------------------------------------------
extern "C" void kernel_launch(void* const* d_in, const int* in_sizes, int n_in,
                              void* d_out, int out_size) {
    const int*   ids   = (const int*)  d_in[0];
    const float* emb   = (const float*)d_in[1];
    const float* W_ih  = (const float*)d_in[2];
    const float* W_hh  = (const float*)d_in[3];
    const float* b_ih  = (const float*)d_in[4];
    const float* b_hh  = (const float*)d_in[5];
    const float* W_dec = (const float*)d_in[6];
    const float* b_dec = (const float*)d_in[7];

    float* out    = (float*)d_out;
    float* logits = out;
    float* hidden = out + ((size_t)out_size - (size_t)NL * BB * HID);

    table_kernel<<<VOCAB, 128>>>(emb, W_ih, b_ih, b_hh);

    size_t smem = SMEM_FLOATS * sizeof(float);
    cudaFuncSetAttribute(rnn_kernel, cudaFuncAttributeMaxDynamicSharedMemorySize,
                         (int)smem);
    rnn_kernel<<<NCTA, NTHR, smem>>>(ids, W_ih, W_hh, b_ih, b_hh,
                                     W_dec, b_dec, logits, hidden);
}